// round 12
// baseline (speedup 1.0000x reference)
#include <cuda_runtime.h>
#include <cstdint>

// YOLO loss v5: obj-cell compaction + warp-cooperative heavy path.
// Light phase: per-thread scattered loads of (t0, p0, p5) for all cells
// (the mandatory DRAM pattern). Obj cells (~5%) are compacted into a
// deterministic smem queue, then processed one-cell-per-warp with two
// coalesced row loads (pc[lane], tc[lane]) + shuffles, eliminating the
// ~19 scattered 1.6-lane loads per divergent warp of previous rounds.
// Fused deterministic reduction (ticket + last block).

#define YS2      49
#define NT       256
#define NWARP    (NT / 32)
#define CPT      2
#define CPB      (NT * CPT)        // 512 cells per block
#define NB       784               // 401408 / 512
#define NBATCH   8192.0

__device__ double       g_partials[NB];
__device__ unsigned int g_ticket;      // zero-init; reset by last block

__global__ __launch_bounds__(NT) void yolo_loss_kernel(
    const float* __restrict__ pred, const float* __restrict__ tgt,
    float* __restrict__ out)
{
    __shared__ uint16_t     queue[CPB];
    __shared__ uint32_t     s_mask[NWARP][CPT];
    __shared__ uint16_t     s_off[NWARP][CPT];
    __shared__ int          s_total;
    __shared__ float        wsum[NWARP];
    __shared__ int          s_last;

    const int tid   = threadIdx.x;
    const int lane  = tid & 31;
    const int wrp   = tid >> 5;
    const int bbase = blockIdx.x * CPB;

    // ================= light phase =================
    float  t0[CPT];
    float2 f01[CPT], f45[CPT];
    #pragma unroll
    for (int k = 0; k < CPT; k++) {
        const int c = bbase + k * NT + tid;
        const float* pc = pred + (size_t)c * 30;
        t0[k]  = __ldg(tgt + (size_t)c * 25);
        f01[k] = __ldg((const float2*)pc);
        f45[k] = __ldg((const float2*)(pc + 4));
    }

    float acc = 0.0f;
    #pragma unroll
    for (int k = 0; k < CPT; k++) {
        const float p0 = f01[k].x, p5 = f45[k].y;
        if (t0[k] == 0.0f) acc += 0.5f * (p0 * p0 + p5 * p5);
    }

    // ================= enqueue obj cells (deterministic) =================
    #pragma unroll
    for (int k = 0; k < CPT; k++) {
        const uint32_t m = __ballot_sync(0xffffffffu, t0[k] == 1.0f);
        if (lane == 0) s_mask[wrp][k] = m;
    }
    __syncthreads();

    if (tid == 0) {
        int run = 0;
        #pragma unroll
        for (int w = 0; w < NWARP; w++)
            #pragma unroll
            for (int k = 0; k < CPT; k++) {
                s_off[w][k] = (uint16_t)run;
                run += __popc(s_mask[w][k]);
            }
        s_total = run;
    }
    __syncthreads();

    #pragma unroll
    for (int k = 0; k < CPT; k++) {
        if (t0[k] == 1.0f) {
            const uint32_t m  = s_mask[wrp][k];
            const int pos = s_off[wrp][k] + __popc(m & ((1u << lane) - 1u));
            queue[pos] = (uint16_t)(k * NT + tid);
        }
    }
    __syncthreads();

    const int total = s_total;

    // ================= heavy phase: one warp per obj cell =================
    float wacc = 0.0f;   // identical on all lanes of the warp
    for (int q = wrp; q < total; q += NWARP) {
        const int cell = bbase + (int)queue[q];
        const float* pc = pred + (size_t)cell * 30;
        const float* tc = tgt  + (size_t)cell * 25;

        // two coalesced row loads cover all 55 floats
        const float pv = (lane < 30) ? __ldg(pc + lane) : 0.0f;
        const float tv = (lane < 25) ? __ldg(tc + lane) : 0.0f;

        // distribute scalars
        const float p0  = __shfl_sync(0xffffffffu, pv, 0);
        const float b0x = __shfl_sync(0xffffffffu, pv, 1);
        const float b0y = __shfl_sync(0xffffffffu, pv, 2);
        const float b0w = __shfl_sync(0xffffffffu, pv, 3);
        const float b0h = __shfl_sync(0xffffffffu, pv, 4);
        const float p5  = __shfl_sync(0xffffffffu, pv, 5);
        const float b1x = __shfl_sync(0xffffffffu, pv, 6);
        const float b1y = __shfl_sync(0xffffffffu, pv, 7);
        const float b1w = __shfl_sync(0xffffffffu, pv, 8);
        const float b1h = __shfl_sync(0xffffffffu, pv, 9);
        const float tx  = __shfl_sync(0xffffffffu, tv, 1);
        const float ty  = __shfl_sync(0xffffffffu, tv, 2);
        const float tw  = __shfl_sync(0xffffffffu, tv, 3);
        const float th  = __shfl_sync(0xffffffffu, tv, 4);

        // cls: lane-parallel over 20 classes, bfly reduce
        const float pcls = __shfl_sync(0xffffffffu, pv, 10 + lane);
        const float tcls = __shfl_sync(0xffffffffu, tv, 5 + lane);
        float d = (lane < 20) ? (pcls - tcls) : 0.0f;
        float cls = d * d;
        #pragma unroll
        for (int o = 16; o > 0; o >>= 1)
            cls += __shfl_xor_sync(0xffffffffu, cls, o);

        // geometry (identical redundant compute on all lanes)
        const int g    = cell % YS2;
        const float gy = (float)(g / 7);
        const float gx = (float)(g % 7);

        const float tcx = (gx + tx) / 7.0f;
        const float tcy = (gy + ty) / 7.0f;
        const float tx1 = tcx - tw * 0.5f, ty1 = tcy - th * 0.5f;
        const float tx2 = tcx + tw * 0.5f, ty2 = tcy + th * 0.5f;
        const float area_t = (tx2 - tx1) * (ty2 - ty1);

        float bx[2][4] = { { b0x, b0y, b0w, b0h },
                           { b1x, b1y, b1w, b1h } };
        float iou[2];
        #pragma unroll
        for (int bb = 0; bb < 2; bb++) {
            const float px = fabsf(bx[bb][0]);
            const float py = fabsf(bx[bb][1]);
            const float pw = fabsf(bx[bb][2]);
            const float ph = fabsf(bx[bb][3]);
            const float cx = (gx + px) / 7.0f;
            const float cy = (gy + py) / 7.0f;
            const float x1 = cx - pw * 0.5f, y1 = cy - ph * 0.5f;
            const float x2 = cx + pw * 0.5f, y2 = cy + ph * 0.5f;
            const float ltx = fmaxf(x1, tx1), lty = fmaxf(y1, ty1);
            const float rbx = fminf(x2, tx2), rby = fminf(y2, ty2);
            const float iw  = fmaxf(rbx - ltx, 0.0f);
            const float ih  = fmaxf(rby - lty, 0.0f);
            const float inter  = iw * ih;
            const float area_p = (x2 - x1) * (y2 - y1);
            iou[bb] = inter / (area_p + area_t - inter);
        }

        const int   best    = (iou[1] > iou[0]) ? 1 : 0;  // tie -> box 0
        const float max_iou = best ? iou[1] : iou[0];
        const float rconf   = best ? p5 : p0;

        const float dx = bx[best][0] - tx;
        const float dy = bx[best][1] - ty;
        const float xy_loss = dx * dx + dy * dy;

        const float swd = sqrtf(fabsf(bx[best][2])) - sqrtf(fabsf(tw));
        const float shd = sqrtf(fabsf(bx[best][3])) - sqrtf(fabsf(th));
        const float wh_loss = swd * swd + shd * shd;

        const float doc = rconf - max_iou;

        wacc += 5.0f * (xy_loss + wh_loss) + doc * doc + cls;
    }

    // fold warp-cooperative sum into lane 0's per-thread value
    if (lane == 0) acc += wacc;

    // ================= deterministic block reduction =================
    #pragma unroll
    for (int o = 16; o > 0; o >>= 1)
        acc += __shfl_down_sync(0xffffffffu, acc, o);

    if (lane == 0) wsum[wrp] = acc;
    __syncthreads();

    if (tid == 0) {
        double s = 0.0;
        #pragma unroll
        for (int w = 0; w < NWARP; w++) s += (double)wsum[w];
        g_partials[blockIdx.x] = s;
        __threadfence();
        unsigned int ticket = atomicAdd(&g_ticket, 1u);
        s_last = (ticket == NB - 1u) ? 1 : 0;
    }
    __syncthreads();

    // ================= last block: final reduction =================
    if (s_last) {
        __threadfence();
        __shared__ double dsum[NWARP];

        double s = 0.0;
        for (int i = tid; i < NB; i += NT)
            s += g_partials[i];

        #pragma unroll
        for (int o = 16; o > 0; o >>= 1)
            s += __shfl_down_sync(0xffffffffu, s, o);

        if (lane == 0) dsum[wrp] = s;
        __syncthreads();

        if (tid == 0) {
            double total_d = 0.0;
            #pragma unroll
            for (int w = 0; w < NWARP; w++) total_d += dsum[w];
            out[0] = (float)(total_d / NBATCH);
            g_ticket = 0;   // reset for next graph replay
        }
    }
}

extern "C" void kernel_launch(void* const* d_in, const int* in_sizes, int n_in,
                              void* d_out, int out_size)
{
    const float* pred = (const float*)d_in[0];
    const float* tgt  = (const float*)d_in[1];
    float* out        = (float*)d_out;

    yolo_loss_kernel<<<NB, NT>>>(pred, tgt, out);
}